// round 4
// baseline (speedup 1.0000x reference)
#include <cuda_runtime.h>
#include <math.h>
#include <stdint.h>

#define BATCH 8192
#define INDIM 512
#define EMB   64
#define KC    256
#define DENSE 1152

// ---------------- scratch globals (tf32 hi/lo interleaved planes) -----------
__device__ float g_xs  [BATCH * 2 * INDIM];
__device__ float g_h1s [BATCH * 2 * DENSE];
__device__ float g_h2s [BATCH * 2 * DENSE];
__device__ float g_encs[BATCH * 2 * EMB];
__device__ float g_smps[BATCH * 2 * EMB];
__device__ float g_eW1s[DENSE * 2 * INDIM];
__device__ float g_eW2s[DENSE * 2 * DENSE];
__device__ float g_eW3s[EMB   * 2 * DENSE];
__device__ float g_dW1s[DENSE * 2 * EMB];
__device__ float g_dW2s[DENSE * 2 * DENSE];
__device__ float g_dW3s[INDIM * 2 * DENSE];
__device__ float g_Ms  [KC * EMB * 2 * EMB];   // M = L^{-1}, split, [k][n][2*64]
__device__ float g_Lraw[KC * EMB * EMB];
__device__ float g_t[KC * EMB];
__device__ float g_c[KC];
__device__ float g_lpT[KC * BATCH];
__device__ int   g_idx[BATCH];

__device__ __forceinline__ float selu_f(float x) {
    const float alpha = 1.6732632423543772f;
    const float scale = 1.0507009873554805f;
    return scale * (x > 0.f ? x : alpha * expm1f(x));
}

// ---------------- ptx helpers ----------------------------------------------
__device__ __forceinline__ void cpa16(void* d, const void* s) {
    uint32_t a = (uint32_t)__cvta_generic_to_shared(d);
    asm volatile("cp.async.cg.shared.global [%0],[%1],16;" :: "r"(a), "l"(s));
}
__device__ __forceinline__ void cp_commit() { asm volatile("cp.async.commit_group;"); }
template <int N> __device__ __forceinline__ void cp_wait() {
    asm volatile("cp.async.wait_group %0;" :: "n"(N));
}
__device__ __forceinline__ void split_tf32(float v, uint32_t& hi, uint32_t& lo) {
    uint32_t h; asm("cvt.rna.tf32.f32 %0,%1;" : "=r"(h) : "f"(v));
    float r = v - __uint_as_float(h);
    uint32_t l; asm("cvt.rna.tf32.f32 %0,%1;" : "=r"(l) : "f"(r));
    hi = h; lo = l;
}
__device__ __forceinline__ void mma8(float* c, const uint32_t* a, const uint32_t* b) {
    asm volatile(
        "mma.sync.aligned.m16n8k8.row.col.f32.tf32.tf32.f32 "
        "{%0,%1,%2,%3},{%4,%5,%6,%7},{%8,%9},{%0,%1,%2,%3};"
        : "+f"(c[0]), "+f"(c[1]), "+f"(c[2]), "+f"(c[3])
        : "r"(a[0]), "r"(a[1]), "r"(a[2]), "r"(a[3]), "r"(b[0]), "r"(b[1]));
}

// ---------------- split fp32 matrix -> interleaved hi/lo --------------------
__global__ void split_mat(const float* __restrict__ src, float* __restrict__ dst, int n) {
    int i = blockIdx.x * blockDim.x + threadIdx.x;
    if (i < n) {
        uint32_t h, l;
        split_tf32(src[i], h, l);
        reinterpret_cast<float2*>(dst)[i] = make_float2(__uint_as_float(h), __uint_as_float(l));
    }
}

// ---------------- cluster prep ----------------------------------------------
__device__ void chol64(float (*A)[EMB + 1], float (*L)[EMB + 1], int tid) {
    __shared__ float sdiag;
    for (int j = 0; j < EMB; j++) {
        if (tid == j) {
            float s = A[j][j];
            for (int q = 0; q < j; q++) s -= L[j][q] * L[j][q];
            float d = sqrtf(fmaxf(s, 1e-30f));
            L[j][j] = d; sdiag = d;
        }
        __syncthreads();
        if (tid > j) {
            float s = A[tid][j];
            for (int q = 0; q < j; q++) s -= L[tid][q] * L[j][q];
            L[tid][j] = s / sdiag;
        }
        __syncthreads();
    }
}

__global__ void prep_clusters(const float* __restrict__ cov,
                              const float* __restrict__ means,
                              const float* __restrict__ sizes) {
    __shared__ float sA[EMB][EMB + 1];
    __shared__ float sL[EMB][EMB + 1];
    __shared__ float smu[EMB];
    const int k = blockIdx.x;
    const int tid = threadIdx.x;
    const float* Ck = cov + (size_t)k * EMB * EMB;

    for (int i = 0; i < EMB; i++) { sA[i][tid] = Ck[i * EMB + tid]; sL[i][tid] = 0.f; }
    __syncthreads();
    sA[tid][tid] += 0.005f;
    __syncthreads();
    chol64(sA, sL, tid);

    if (tid == 0) {
        float ld = 0.f;
        for (int j = 0; j < EMB; j++) ld += logf(sL[j][j]);
        g_c[k] = logf(sizes[k]) - 0.5f * (EMB * 1.8378770664093453f) - ld;
    }

    for (int i = 0; i < EMB; i++) sA[i][tid] = 0.f;
    __syncthreads();
    {
        const int c = tid;
        for (int i = c; i < EMB; i++) {
            float s = (i == c) ? 1.f : 0.f;
            for (int q = c; q < i; q++) s -= sL[i][q] * sA[q][c];
            sA[i][c] = s / sL[i][i];
        }
    }
    __syncthreads();
    // write split M: g_Ms[k][row r][2*col]
    for (int r = 0; r < EMB; r++) {
        uint32_t h, l;
        split_tf32(sA[r][tid], h, l);
        reinterpret_cast<float2*>(g_Ms + ((size_t)k * EMB + r) * 2 * EMB)[tid] =
            make_float2(__uint_as_float(h), __uint_as_float(l));
    }
    smu[tid] = means[k * EMB + tid];
    __syncthreads();
    {
        float s = 0.f;
        for (int j = 0; j < EMB; j++) s += sA[tid][j] * smu[j];
        g_t[k * EMB + tid] = s;
    }
    __syncthreads();

    for (int i = 0; i < EMB; i++) { sA[i][tid] = Ck[i * EMB + tid]; sL[i][tid] = 0.f; }
    __syncthreads();
    chol64(sA, sL, tid);
    for (int r = 0; r < EMB; r++)
        g_Lraw[(size_t)k * EMB * EMB + r * EMB + tid] = sL[r][tid];
}

// ---------------- pre-split 3xTF32 GEMM -------------------------------------
// C = act(A @ W^T + bias).  A:[M][2K] split, W:[N][2K] split.
// Block BM x 64 (BM=64*MI), 8 warps as 4(m) x 2(n); warp tile (16*MI) x 32.
// SPLIT=1 -> C:[M][2N] interleaved hi/lo; else C:[M][N] fp32.
template <int MI, int ACT, int SPLIT>
__global__ __launch_bounds__(256) void gemm_ts(const float* __restrict__ A,
                                               const float* __restrict__ W,
                                               const float* __restrict__ bias,
                                               float* __restrict__ C,
                                               int M, int N, int K) {
    constexpr int BM = 64 * MI;
    __shared__ float As[2][BM * 24];   // 16 floats per k8 chunk row + 8 pad
    __shared__ float Ws[2][64 * 24];
    const int tid = threadIdx.x;
    const int lane = tid & 31, w = tid >> 5;
    const int gid = lane >> 2, tig = lane & 3;
    const int wm = w >> 1, wn = w & 1;
    const int m0 = blockIdx.y * BM, n0 = blockIdx.x * 64;
    const int K2 = 2 * K;

    float acc[MI][4][4];
#pragma unroll
    for (int i = 0; i < MI; i++)
#pragma unroll
        for (int j = 0; j < 4; j++)
#pragma unroll
            for (int q = 0; q < 4; q++) acc[i][j][q] = 0.f;

    auto load_stage = [&](int s, int k0) {
#pragma unroll
        for (int q = 0; q < MI; q++) {
            int f = tid + q * 256;
            int r = f >> 2, c = f & 3;
            cpa16(&As[s][r * 24 + c * 4], A + (size_t)(m0 + r) * K2 + 2 * k0 + c * 4);
        }
        {
            int r = tid >> 2, c = tid & 3;
            cpa16(&Ws[s][r * 24 + c * 4], W + (size_t)(n0 + r) * K2 + 2 * k0 + c * 4);
        }
    };

    const int nst = K / 8;
    load_stage(0, 0); cp_commit();
    for (int s = 0; s < nst; s++) {
        if (s + 1 < nst) { load_stage((s + 1) & 1, (s + 1) * 8); cp_commit(); cp_wait<1>(); }
        else cp_wait<0>();
        __syncthreads();
        const int bs = s & 1;

        uint32_t ah[MI][4], al[MI][4], bh[4][2], bl[4][2];
#pragma unroll
        for (int mi = 0; mi < MI; mi++) {
            const int r0 = wm * 16 * MI + mi * 16 + gid;
            float2 p0 = *reinterpret_cast<const float2*>(&As[bs][r0 * 24 + 2 * tig]);
            float2 p1 = *reinterpret_cast<const float2*>(&As[bs][(r0 + 8) * 24 + 2 * tig]);
            float2 p2 = *reinterpret_cast<const float2*>(&As[bs][r0 * 24 + 2 * tig + 8]);
            float2 p3 = *reinterpret_cast<const float2*>(&As[bs][(r0 + 8) * 24 + 2 * tig + 8]);
            ah[mi][0] = __float_as_uint(p0.x); al[mi][0] = __float_as_uint(p0.y);
            ah[mi][1] = __float_as_uint(p1.x); al[mi][1] = __float_as_uint(p1.y);
            ah[mi][2] = __float_as_uint(p2.x); al[mi][2] = __float_as_uint(p2.y);
            ah[mi][3] = __float_as_uint(p3.x); al[mi][3] = __float_as_uint(p3.y);
        }
#pragma unroll
        for (int ni = 0; ni < 4; ni++) {
            const int r = wn * 32 + ni * 8 + gid;
            float2 q0 = *reinterpret_cast<const float2*>(&Ws[bs][r * 24 + 2 * tig]);
            float2 q1 = *reinterpret_cast<const float2*>(&Ws[bs][r * 24 + 2 * tig + 8]);
            bh[ni][0] = __float_as_uint(q0.x); bl[ni][0] = __float_as_uint(q0.y);
            bh[ni][1] = __float_as_uint(q1.x); bl[ni][1] = __float_as_uint(q1.y);
        }
#pragma unroll
        for (int mi = 0; mi < MI; mi++)
#pragma unroll
            for (int ni = 0; ni < 4; ni++) {
                mma8(acc[mi][ni], ah[mi], bl[ni]);
                mma8(acc[mi][ni], al[mi], bh[ni]);
                mma8(acc[mi][ni], ah[mi], bh[ni]);
            }
        __syncthreads();
    }

#pragma unroll
    for (int mi = 0; mi < MI; mi++)
#pragma unroll
        for (int ni = 0; ni < 4; ni++) {
            const int row = m0 + wm * 16 * MI + mi * 16 + gid;
            const int col = n0 + wn * 32 + ni * 8 + 2 * tig;
            const float bv0 = __ldg(bias + col), bv1 = __ldg(bias + col + 1);
            float v0 = acc[mi][ni][0] + bv0, v1 = acc[mi][ni][1] + bv1;
            float v2 = acc[mi][ni][2] + bv0, v3 = acc[mi][ni][3] + bv1;
            if (ACT) { v0 = selu_f(v0); v1 = selu_f(v1); v2 = selu_f(v2); v3 = selu_f(v3); }
            if (SPLIT) {
                uint32_t h0, l0, h1, l1;
                split_tf32(v0, h0, l0); split_tf32(v1, h1, l1);
                *reinterpret_cast<float4*>(C + (size_t)row * 2 * N + 2 * col) =
                    make_float4(__uint_as_float(h0), __uint_as_float(l0),
                                __uint_as_float(h1), __uint_as_float(l1));
                split_tf32(v2, h0, l0); split_tf32(v3, h1, l1);
                *reinterpret_cast<float4*>(C + (size_t)(row + 8) * 2 * N + 2 * col) =
                    make_float4(__uint_as_float(h0), __uint_as_float(l0),
                                __uint_as_float(h1), __uint_as_float(l1));
            } else {
                *reinterpret_cast<float2*>(C + (size_t)row * N + col) = make_float2(v0, v1);
                *reinterpret_cast<float2*>(C + (size_t)(row + 8) * N + col) = make_float2(v2, v3);
            }
        }
}

// ---------------- fused quad/log_prob ---------------------------------------
// 1 cluster per block; M (64x64, split) resident in smem; enc streamed.
// Warps: 4(m) x 2(n); warp tile 16 x 32 over (64 batch rows x 64 z-cols).
__global__ __launch_bounds__(256) void quad_kernel() {
    __shared__ float Ms[64 * 136];     // [n][2*64 interleaved + 8 pad]
    __shared__ float Es[2][64 * 24];
    __shared__ float sP[64][2];
    __shared__ float Ts[64];
    __shared__ float cK;
    const int tid = threadIdx.x;
    const int lane = tid & 31, w = tid >> 5;
    const int gid = lane >> 2, tig = lane & 3;
    const int wm = w >> 1, wn = w & 1;
    const int k = blockIdx.x;

#pragma unroll
    for (int q = 0; q < 8; q++) {
        int f = tid + q * 256;          // 2048 float4s
        int r = f >> 5, c4 = f & 31;
        *reinterpret_cast<float4*>(&Ms[r * 136 + c4 * 4]) =
            *reinterpret_cast<const float4*>(g_Ms + ((size_t)k * 64 + r) * 128 + c4 * 4);
    }
    if (tid < 64) Ts[tid] = g_t[k * 64 + tid];
    if (tid == 0) cK = g_c[k];
    __syncthreads();

    for (int tile = 0; tile < BATCH / 64; tile++) {
        const int b0 = tile * 64;
        float acc[4][4];
#pragma unroll
        for (int j = 0; j < 4; j++)
#pragma unroll
            for (int q = 0; q < 4; q++) acc[j][q] = 0.f;

        auto loadE = [&](int s, int ck) {
            int r = tid >> 2, c = tid & 3;
            cpa16(&Es[s][r * 24 + c * 4], g_encs + (size_t)(b0 + r) * 128 + ck * 16 + c * 4);
        };
        loadE(0, 0); cp_commit();
        for (int ck = 0; ck < 8; ck++) {
            if (ck < 7) { loadE((ck + 1) & 1, ck + 1); cp_commit(); cp_wait<1>(); }
            else cp_wait<0>();
            __syncthreads();
            const int bs = ck & 1;
            uint32_t ah[4], al[4], bh[4][2], bl[4][2];
            {
                const int r0 = wm * 16 + gid;
                float2 p0 = *reinterpret_cast<const float2*>(&Es[bs][r0 * 24 + 2 * tig]);
                float2 p1 = *reinterpret_cast<const float2*>(&Es[bs][(r0 + 8) * 24 + 2 * tig]);
                float2 p2 = *reinterpret_cast<const float2*>(&Es[bs][r0 * 24 + 2 * tig + 8]);
                float2 p3 = *reinterpret_cast<const float2*>(&Es[bs][(r0 + 8) * 24 + 2 * tig + 8]);
                ah[0] = __float_as_uint(p0.x); al[0] = __float_as_uint(p0.y);
                ah[1] = __float_as_uint(p1.x); al[1] = __float_as_uint(p1.y);
                ah[2] = __float_as_uint(p2.x); al[2] = __float_as_uint(p2.y);
                ah[3] = __float_as_uint(p3.x); al[3] = __float_as_uint(p3.y);
            }
#pragma unroll
            for (int ni = 0; ni < 4; ni++) {
                const int r = wn * 32 + ni * 8 + gid;
                float2 q0 = *reinterpret_cast<const float2*>(&Ms[r * 136 + ck * 16 + 2 * tig]);
                float2 q1 = *reinterpret_cast<const float2*>(&Ms[r * 136 + ck * 16 + 2 * tig + 8]);
                bh[ni][0] = __float_as_uint(q0.x); bl[ni][0] = __float_as_uint(q0.y);
                bh[ni][1] = __float_as_uint(q1.x); bl[ni][1] = __float_as_uint(q1.y);
            }
#pragma unroll
            for (int ni = 0; ni < 4; ni++) {
                mma8(acc[ni], ah, bl[ni]);
                mma8(acc[ni], al, bh[ni]);
                mma8(acc[ni], ah, bh[ni]);
            }
            __syncthreads();
        }
        // quad = sum_cols (z - t)^2
#pragma unroll
        for (int h = 0; h < 2; h++) {
            float q = 0.f;
#pragma unroll
            for (int ni = 0; ni < 4; ni++) {
                const int col = wn * 32 + ni * 8 + 2 * tig;
                float z0 = acc[ni][2 * h] - Ts[col];
                float z1 = acc[ni][2 * h + 1] - Ts[col + 1];
                q = fmaf(z0, z0, fmaf(z1, z1, q));
            }
            q += __shfl_xor_sync(0xffffffffu, q, 1);
            q += __shfl_xor_sync(0xffffffffu, q, 2);
            if (tig == 0) sP[wm * 16 + gid + 8 * h][wn] = q;
        }
        __syncthreads();
        if (tid < 64) {
            float lp = cK - 0.5f * (sP[tid][0] + sP[tid][1]);
            g_lpT[(size_t)k * BATCH + b0 + tid] = lp;
        }
        __syncthreads();
    }
}

// ---------------- transpose lpT -> out_lp [B][K] ----------------------------
__global__ void transpose_lp(float* __restrict__ out_lp) {
    __shared__ float t[32][33];
    const int bx = blockIdx.x * 32, ky = blockIdx.y * 32;
    const int tx = threadIdx.x, ty = threadIdx.y;
#pragma unroll
    for (int i = 0; i < 4; i++)
        t[ty + 8 * i][tx] = g_lpT[(size_t)(ky + ty + 8 * i) * BATCH + bx + tx];
    __syncthreads();
#pragma unroll
    for (int i = 0; i < 4; i++)
        out_lp[(size_t)(bx + ty + 8 * i) * KC + ky + tx] = t[tx][ty + 8 * i];
}

// ---------------- argmax (first-max-wins) -----------------------------------
__global__ void argmax_kernel(const float* __restrict__ lp, float* __restrict__ out_idx) {
    const int row = blockIdx.x * 8 + (threadIdx.x >> 5);
    const int lane = threadIdx.x & 31;
    float best = -3.4e38f; int bi = 0;
#pragma unroll
    for (int q = 0; q < 2; q++) {
        const int k = lane * 4 + q * 128;
        float4 v = *reinterpret_cast<const float4*>(lp + (size_t)row * KC + k);
        if (v.x > best) { best = v.x; bi = k; }
        if (v.y > best) { best = v.y; bi = k + 1; }
        if (v.z > best) { best = v.z; bi = k + 2; }
        if (v.w > best) { best = v.w; bi = k + 3; }
    }
#pragma unroll
    for (int o = 16; o; o >>= 1) {
        float ov = __shfl_xor_sync(0xffffffffu, best, o);
        int oi = __shfl_xor_sync(0xffffffffu, bi, o);
        if (ov > best || (ov == best && oi < bi)) { best = ov; bi = oi; }
    }
    if (lane == 0) { g_idx[row] = bi; out_idx[row] = (float)bi; }
}

// ---------------- sample = means[idx] + L_raw[idx] @ noise (split out) ------
__global__ void sample_kernel(const float* __restrict__ means,
                              const float* __restrict__ noise) {
    __shared__ float sn[EMB];
    const int bb = blockIdx.x;
    const int i = threadIdx.x;
    sn[i] = noise[(size_t)bb * EMB + i];
    __syncthreads();
    const int k = g_idx[bb];
    const float* Lr = g_Lraw + (size_t)k * EMB * EMB + i * EMB;
    float s = means[k * EMB + i];
    for (int j = 0; j <= i; j++) s = fmaf(Lr[j], sn[j], s);
    uint32_t h, l;
    split_tf32(s, h, l);
    reinterpret_cast<float2*>(g_smps + (size_t)bb * 2 * EMB)[i] =
        make_float2(__uint_as_float(h), __uint_as_float(l));
}

// ---------------- launch ----------------------------------------------------
extern "C" void kernel_launch(void* const* d_in, const int* in_sizes, int n_in,
                              void* d_out, int out_size) {
    const float* x     = (const float*)d_in[0];
    const float* noise = (const float*)d_in[1];
    const float* eW1 = (const float*)d_in[2];  const float* eb1 = (const float*)d_in[3];
    const float* eW2 = (const float*)d_in[4];  const float* eb2 = (const float*)d_in[5];
    const float* eW3 = (const float*)d_in[6];  const float* eb3 = (const float*)d_in[7];
    const float* dW1 = (const float*)d_in[8];  const float* db1 = (const float*)d_in[9];
    const float* dW2 = (const float*)d_in[10]; const float* db2 = (const float*)d_in[11];
    const float* dW3 = (const float*)d_in[12]; const float* db3 = (const float*)d_in[13];
    const float* means = (const float*)d_in[14];
    const float* sizes = (const float*)d_in[15];
    const float* cov   = (const float*)d_in[16];

    float* out = (float*)d_out;
    float* out_dec = out;
    float* out_lp  = out + (size_t)BATCH * INDIM;
    float* out_idx = out + (size_t)BATCH * (INDIM + KC);

    float *xs, *h1s, *h2s, *encs, *smps, *eW1s, *eW2s, *eW3s, *dW1s, *dW2s, *dW3s;
    cudaGetSymbolAddress((void**)&xs,  g_xs);
    cudaGetSymbolAddress((void**)&h1s, g_h1s);
    cudaGetSymbolAddress((void**)&h2s, g_h2s);
    cudaGetSymbolAddress((void**)&encs, g_encs);
    cudaGetSymbolAddress((void**)&smps, g_smps);
    cudaGetSymbolAddress((void**)&eW1s, g_eW1s);
    cudaGetSymbolAddress((void**)&eW2s, g_eW2s);
    cudaGetSymbolAddress((void**)&eW3s, g_eW3s);
    cudaGetSymbolAddress((void**)&dW1s, g_dW1s);
    cudaGetSymbolAddress((void**)&dW2s, g_dW2s);
    cudaGetSymbolAddress((void**)&dW3s, g_dW3s);

    // pre-split x and weights (one pass each)
    split_mat<<<(BATCH * INDIM + 255) / 256, 256>>>(x, xs, BATCH * INDIM);
    split_mat<<<(DENSE * INDIM + 255) / 256, 256>>>(eW1, eW1s, DENSE * INDIM);
    split_mat<<<(DENSE * DENSE + 255) / 256, 256>>>(eW2, eW2s, DENSE * DENSE);
    split_mat<<<(EMB * DENSE + 255) / 256, 256>>>(eW3, eW3s, EMB * DENSE);
    split_mat<<<(DENSE * EMB + 255) / 256, 256>>>(dW1, dW1s, DENSE * EMB);
    split_mat<<<(DENSE * DENSE + 255) / 256, 256>>>(dW2, dW2s, DENSE * DENSE);
    split_mat<<<(INDIM * DENSE + 255) / 256, 256>>>(dW3, dW3s, INDIM * DENSE);

    prep_clusters<<<KC, EMB>>>(cov, means, sizes);

    // encoder
    gemm_ts<2, 1, 1><<<dim3(DENSE / 64, BATCH / 128), 256>>>(xs,  eW1s, eb1, h1s, BATCH, DENSE, INDIM);
    gemm_ts<2, 1, 1><<<dim3(DENSE / 64, BATCH / 128), 256>>>(h1s, eW2s, eb2, h2s, BATCH, DENSE, DENSE);
    gemm_ts<1, 0, 1><<<dim3(EMB / 64, BATCH / 64), 256>>>(h2s, eW3s, eb3, encs, BATCH, EMB, DENSE);

    // quantize
    quad_kernel<<<KC, 256>>>();
    transpose_lp<<<dim3(BATCH / 32, KC / 32), dim3(32, 8)>>>(out_lp);
    argmax_kernel<<<BATCH / 8, 256>>>(out_lp, out_idx);
    sample_kernel<<<BATCH, EMB>>>(means, noise);

    // decoder
    gemm_ts<2, 1, 1><<<dim3(DENSE / 64, BATCH / 128), 256>>>(smps, dW1s, db1, h1s, BATCH, DENSE, EMB);
    gemm_ts<2, 1, 1><<<dim3(DENSE / 64, BATCH / 128), 256>>>(h1s, dW2s, db2, h2s, BATCH, DENSE, DENSE);
    gemm_ts<2, 0, 0><<<dim3(INDIM / 64, BATCH / 128), 256>>>(h2s, dW3s, db3, out_dec, BATCH, INDIM, DENSE);
}